// round 13
// baseline (speedup 1.0000x reference)
#include <cuda_runtime.h>
#include <cstdint>

#define NB 8
#define NP 1024
#define KNN 20
#define M3 (3*NP)
#define EPSV 1e-6f

// ---------------- scratch (device globals; no allocations allowed) ----------------
__device__ float g_nd[(size_t)NB*NP*NP];     // neg-distance matrix (B,N,N)
__device__ int   g_idx[NB*NP*KNN];           // knn indices
__device__ float g_Ws[342*169];              // stacked/transformed weights (max 342x169)
__device__ float g_C[(size_t)NB*342*M3];     // gemm output (Af/Bf/Ad/Bd stacked, or p/d for layer4)
__device__ float g_xcat[(size_t)NB*169*M3];  // concat feature buffer (B,169,3,N)

// ---------------- weight prep: stack [WfA; WfB-WfA; WdA; WdB-WdA] -> (4Co x D) ----
__global__ void prepw_kernel(const float* __restrict__ Wf, const float* __restrict__ Wd,
                             int Co, int D) {
    int t = blockIdx.x * blockDim.x + threadIdx.x;
    int total = 4 * Co * D;
    if (t >= total) return;
    int ci = t % D;
    int r  = t / D;
    float v;
    if (r < Co) {
        v = Wf[r * 2 * D + ci];
    } else if (r < 2 * Co) {
        int co = r - Co;
        v = Wf[co * 2 * D + D + ci] - Wf[co * 2 * D + ci];
    } else if (r < 3 * Co) {
        int co = r - 2 * Co;
        v = Wd[co * 2 * D + ci];
    } else {
        int co = r - 3 * Co;
        v = Wd[co * 2 * D + D + ci] - Wd[co * 2 * D + ci];
    }
    g_Ws[t] = v;
}

// layer4: stack [Wf4 (341x169); Wd4 (1x169)] -> (342x169)
__global__ void prepw4_kernel(const float* __restrict__ Wf, const float* __restrict__ Wd) {
    int t = blockIdx.x * blockDim.x + threadIdx.x;
    const int nf = 341 * 169;
    const int total = 342 * 169;
    if (t >= total) return;
    g_Ws[t] = (t < nf) ? Wf[t] : Wd[t - nf];
}

// ---------------- negdist (SYMMETRIC): nd[i][j] = 2*<xi,xj> - xx_i - xx_j --------
__global__ __launch_bounds__(256) void negdist_kernel(const float* __restrict__ X,
                                                      int Ctot, int coff, int F) {
    int b = blockIdx.z;
    int bi = 0, rem = blockIdx.x;
    while (rem >= 8 - bi) { rem -= 8 - bi; ++bi; }
    int bj = bi + rem;
    int i0 = bi * 128;
    int j0 = bj * 128;

    __shared__ float sA[8][128];
    __shared__ float sB[8][128];
    __shared__ float sT[16][132];     // transpose staging; 132-float stride = 528B = 33*16B
    const int t  = threadIdx.x;
    const int tx = t & 15, ty = t >> 4;
    const int lk = t >> 5;
    const int lc = (t & 31) * 4;
    float acc[8][8] = {};
    float xxa[8] = {}, xxb[8] = {};
    const float* Xb = X + (size_t)(b * Ctot + coff) * M3;
    const int nch = (F + 7) / 8;
    for (int c = 0; c < nch; ++c) {
        int f = c * 8 + lk;
        float4 va = make_float4(0.f, 0.f, 0.f, 0.f), vb = va;
        if (f < F) {
            va = *reinterpret_cast<const float4*>(&Xb[(size_t)f * NP + i0 + lc]);
            vb = *reinterpret_cast<const float4*>(&Xb[(size_t)f * NP + j0 + lc]);
        }
        *reinterpret_cast<float4*>(&sA[lk][lc]) = va;
        *reinterpret_cast<float4*>(&sB[lk][lc]) = vb;
        __syncthreads();
        #pragma unroll
        for (int kk = 0; kk < 8; ++kk) {
            float4 a0 = *reinterpret_cast<const float4*>(&sA[kk][ty * 8]);
            float4 a1 = *reinterpret_cast<const float4*>(&sA[kk][ty * 8 + 4]);
            float4 b0 = *reinterpret_cast<const float4*>(&sB[kk][tx * 8]);
            float4 b1 = *reinterpret_cast<const float4*>(&sB[kk][tx * 8 + 4]);
            float av[8] = {a0.x, a0.y, a0.z, a0.w, a1.x, a1.y, a1.z, a1.w};
            float bv[8] = {b0.x, b0.y, b0.z, b0.w, b1.x, b1.y, b1.z, b1.w};
            #pragma unroll
            for (int i = 0; i < 8; ++i) {
                xxa[i] += av[i] * av[i];
                xxb[i] += bv[i] * bv[i];
                #pragma unroll
                for (int j = 0; j < 8; ++j)
                    acc[i][j] += av[i] * bv[j];
            }
        }
        __syncthreads();
    }
    float* ndb = g_nd + (size_t)b * NP * NP;

    #pragma unroll
    for (int i = 0; i < 8; ++i) {
        int ii = i0 + ty * 8 + i;
        float xi = xxa[i];
        float4 v0, v1;
        v0.x = 2.f * acc[i][0] - xi - xxb[0];
        v0.y = 2.f * acc[i][1] - xi - xxb[1];
        v0.z = 2.f * acc[i][2] - xi - xxb[2];
        v0.w = 2.f * acc[i][3] - xi - xxb[3];
        v1.x = 2.f * acc[i][4] - xi - xxb[4];
        v1.y = 2.f * acc[i][5] - xi - xxb[5];
        v1.z = 2.f * acc[i][6] - xi - xxb[6];
        v1.w = 2.f * acc[i][7] - xi - xxb[7];
        float* rowp = &ndb[(size_t)ii * NP + j0 + tx * 8];
        *reinterpret_cast<float4*>(rowp)     = v0;
        *reinterpret_cast<float4*>(rowp + 4) = v1;
    }

    if (bi != bj) {
        __syncthreads();
        #pragma unroll 1
        for (int c = 0; c < 8; ++c) {
            if ((tx >> 1) == c) {
                int colbase = (tx & 1) * 8;
                #pragma unroll
                for (int j = 0; j < 8; ++j) {
                    #pragma unroll
                    for (int i = 0; i < 8; ++i) {
                        sT[colbase + j][ty * 8 + i] = (2.f * acc[i][j] - xxb[j]) - xxa[i];
                    }
                }
            }
            __syncthreads();
            {
                int r    = t >> 4;
                int colS = (t & 15) * 8;
                float4 u0 = *reinterpret_cast<const float4*>(&sT[r][colS]);
                float4 u1 = *reinterpret_cast<const float4*>(&sT[r][colS + 4]);
                float* orow = &ndb[(size_t)(j0 + c * 16 + r) * NP + i0 + colS];
                *reinterpret_cast<float4*>(orow)     = u0;
                *reinterpret_cast<float4*>(orow + 4) = u1;
            }
            __syncthreads();
        }
    }
}

// ---------------- topk: radix-bin select, TWO rows per block -------------------
// Row A and row B loads are issued together; row B's histogram accumulation
// overlaps row A's warp-0 boundary selection. Identical per-row algorithm to the
// proven single-row version (order-free set; lowest-index tie-break).
__device__ __forceinline__ unsigned int f2key(float v) {
    unsigned int u = __float_as_uint(v);
    return (u & 0x80000000u) ? ~u : (u | 0x80000000u);   // monotonic: bigger float -> bigger key
}

__global__ __launch_bounds__(256) void topk_kernel() {
    const int rowA = blockIdx.x * 2;
    const int rowB = rowA + 1;
    __shared__ int histA[1024];
    __shared__ int histB[1024];
    __shared__ int cand_key_i[NP];         // reused for both rows (A's selection ends
    __shared__ int cand_idx[NP];           //  before B's scatter; sync-separated)
    __shared__ int sP[256];
    __shared__ int sG[256];
    __shared__ int wsum[8];
    __shared__ int sh_B, sh_c, sh_ncand, sh_nout;

    const int t   = threadIdx.x;
    const int wid = t >> 5, lid = t & 31;

    // P0: issue BOTH row loads (2x MLP), zero histA
    const float4 vA = reinterpret_cast<const float4*>(g_nd + (size_t)rowA * NP)[t];
    const float4 vB = reinterpret_cast<const float4*>(g_nd + (size_t)rowB * NP)[t];
    reinterpret_cast<int4*>(histA)[t] = make_int4(0, 0, 0, 0);
    if (t == 0) { sh_ncand = 0; sh_nout = 0; }
    __syncthreads();

    // P1: row A histogram
    unsigned int keysA[4];
    keysA[0] = f2key(vA.x); keysA[1] = f2key(vA.y); keysA[2] = f2key(vA.z); keysA[3] = f2key(vA.w);
    #pragma unroll
    for (int i = 0; i < 4; ++i) atomicAdd(&histA[keysA[i] >> 22], 1);
    __syncthreads();

    // P2: row A scan + boundary
    {
        int4 h4 = reinterpret_cast<const int4*>(histA)[t];
        sP[t] = h4.x + h4.y + h4.z + h4.w;
    }
    __syncthreads();
    {
        int s = sP[255 - t];
        #pragma unroll
        for (int off = 1; off < 32; off <<= 1) {
            int n = __shfl_up_sync(0xffffffffu, s, off);
            if (lid >= off) s += n;
        }
        if (lid == 31) wsum[wid] = s;
        __syncthreads();
        int add = 0;
        #pragma unroll
        for (int w = 0; w < 8; ++w) if (w < wid) add += wsum[w];
        sG[255 - t] = s + add;
    }
    __syncthreads();
    {
        int Gt    = sG[t];
        int Gnext = (t < 255) ? sG[t + 1] : 0;
        if (Gt >= KNN && Gnext < KNN) {
            int cum = Gnext;
            int B = 4 * t;
            #pragma unroll
            for (int b = 4 * t + 3; b >= 4 * t; --b) {
                int h = histA[b];
                if (cum + h >= KNN) { B = b; break; }
                cum += h;
            }
            sh_B = B; sh_c = cum;
        }
    }
    __syncthreads();
    {
        const int B = sh_B;
        const int c = sh_c;
        int* outp = g_idx + (size_t)rowA * KNN;

        // P3: scatter A winners/candidates; zero histB in the same phase
        #pragma unroll
        for (int i = 0; i < 4; ++i) {
            int j = 4 * t + i;
            int bin = keysA[i] >> 22;
            if (bin > B) {
                int pos = atomicAdd(&sh_nout, 1);
                outp[pos] = j;
            } else if (bin == B) {
                int pos = atomicAdd(&sh_ncand, 1);
                cand_key_i[pos] = (int)keysA[i];
                cand_idx[pos] = j;
            }
        }
        reinterpret_cast<int4*>(histB)[t] = make_int4(0, 0, 0, 0);
        __syncthreads();

        // P4: warp 0 does row A selection; meanwhile all warps add row B histogram
        unsigned int keysB[4];
        keysB[0] = f2key(vB.x); keysB[1] = f2key(vB.y); keysB[2] = f2key(vB.z); keysB[3] = f2key(vB.w);
        if (wid == 0) {
            const int m = sh_ncand;
            const int rneed = KNN - c;
            for (int sel = 0; sel < rneed; ++sel) {
                unsigned long long best = 0ull;
                for (int j = lid; j < m; j += 32) {
                    unsigned int key = (unsigned int)cand_key_i[j];
                    if (key != 0u) {
                        unsigned long long p = ((unsigned long long)key << 32)
                                             | ((unsigned long long)(1023 - cand_idx[j]) << 10)
                                             | (unsigned int)j;
                        if (p > best) best = p;
                    }
                }
                #pragma unroll
                for (int off = 16; off > 0; off >>= 1) {
                    unsigned long long o = __shfl_xor_sync(0xffffffffu, best, off);
                    if (o > best) best = o;
                }
                int candpos = (int)(best & 1023ull);
                if (lid == 0) {
                    outp[c + sel] = cand_idx[candpos];
                    cand_key_i[candpos] = 0;
                }
                __syncwarp();
            }
            if (lid == 0) { sh_ncand = 0; sh_nout = 0; }   // reset for row B
        }
        #pragma unroll
        for (int i = 0; i < 4; ++i) atomicAdd(&histB[keysB[i] >> 22], 1);
        __syncthreads();

        // P5: row B scan + boundary
        {
            int4 h4 = reinterpret_cast<const int4*>(histB)[t];
            sP[t] = h4.x + h4.y + h4.z + h4.w;
        }
        __syncthreads();
        {
            int s = sP[255 - t];
            #pragma unroll
            for (int off = 1; off < 32; off <<= 1) {
                int n = __shfl_up_sync(0xffffffffu, s, off);
                if (lid >= off) s += n;
            }
            if (lid == 31) wsum[wid] = s;
            __syncthreads();
            int add = 0;
            #pragma unroll
            for (int w = 0; w < 8; ++w) if (w < wid) add += wsum[w];
            sG[255 - t] = s + add;
        }
        __syncthreads();
        {
            int Gt    = sG[t];
            int Gnext = (t < 255) ? sG[t + 1] : 0;
            if (Gt >= KNN && Gnext < KNN) {
                int cum = Gnext;
                int B2 = 4 * t;
                #pragma unroll
                for (int b = 4 * t + 3; b >= 4 * t; --b) {
                    int h = histB[b];
                    if (cum + h >= KNN) { B2 = b; break; }
                    cum += h;
                }
                sh_B = B2; sh_c = cum;
            }
        }
        __syncthreads();

        // P6: scatter B winners/candidates
        const int B2 = sh_B;
        const int c2 = sh_c;
        int* outpB = g_idx + (size_t)rowB * KNN;
        #pragma unroll
        for (int i = 0; i < 4; ++i) {
            int j = 4 * t + i;
            int bin = keysB[i] >> 22;
            if (bin > B2) {
                int pos = atomicAdd(&sh_nout, 1);
                outpB[pos] = j;
            } else if (bin == B2) {
                int pos = atomicAdd(&sh_ncand, 1);
                cand_key_i[pos] = (int)keysB[i];
                cand_idx[pos] = j;
            }
        }
        __syncthreads();

        // P7: warp 0 row B selection
        if (wid == 0) {
            const int m = sh_ncand;
            const int rneed = KNN - c2;
            for (int sel = 0; sel < rneed; ++sel) {
                unsigned long long best = 0ull;
                for (int j = lid; j < m; j += 32) {
                    unsigned int key = (unsigned int)cand_key_i[j];
                    if (key != 0u) {
                        unsigned long long p = ((unsigned long long)key << 32)
                                             | ((unsigned long long)(1023 - cand_idx[j]) << 10)
                                             | (unsigned int)j;
                        if (p > best) best = p;
                    }
                }
                #pragma unroll
                for (int off = 16; off > 0; off >>= 1) {
                    unsigned long long o = __shfl_xor_sync(0xffffffffu, best, off);
                    if (o > best) best = o;
                }
                int candpos = (int)(best & 1023ull);
                if (lid == 0) {
                    outpB[c2 + sel] = cand_idx[candpos];
                    cand_key_i[candpos] = 0;
                }
                __syncwarp();
            }
        }
    }
}

// ---------------- gemm: C[b, row, m] = sum_ci Ws[row, ci] * X[b, ci, m] ----------
// 128x128 tile, 8x8 register microtile, BK=8.
__global__ __launch_bounds__(256) void gemm_wx(const float* __restrict__ X, int Ctot, int xOff,
                                               int Mrows, int K) {
    int b  = blockIdx.z;
    int m0 = blockIdx.y * 128;
    int n0 = blockIdx.x * 128;
    __shared__ float sW[8][128];
    __shared__ float sX[8][128];
    const int t  = threadIdx.x;
    const int tx = t & 15, ty = t >> 4;
    const int lk = t >> 5;
    const int lc = (t & 31) * 4;
    float acc[8][8] = {};
    const float* Xb = X + (size_t)(b * Ctot + xOff) * M3;
    const int nch = (K + 7) / 8;
    for (int c = 0; c < nch; ++c) {
        #pragma unroll
        for (int i = t; i < 1024; i += 256) {
            int kk = i & 7, mo = i >> 3;
            int row = m0 + mo, col = c * 8 + kk;
            sW[kk][mo] = (row < Mrows && col < K) ? g_Ws[row * K + col] : 0.f;
        }
        int f = c * 8 + lk;
        float4 vx = make_float4(0.f, 0.f, 0.f, 0.f);
        if (f < K) vx = *reinterpret_cast<const float4*>(&Xb[(size_t)f * M3 + n0 + lc]);
        *reinterpret_cast<float4*>(&sX[lk][lc]) = vx;
        __syncthreads();
        #pragma unroll
        for (int kk = 0; kk < 8; ++kk) {
            float4 w0 = *reinterpret_cast<const float4*>(&sW[kk][ty * 8]);
            float4 w1 = *reinterpret_cast<const float4*>(&sW[kk][ty * 8 + 4]);
            float4 x0 = *reinterpret_cast<const float4*>(&sX[kk][tx * 8]);
            float4 x1 = *reinterpret_cast<const float4*>(&sX[kk][tx * 8 + 4]);
            float wv[8] = {w0.x, w0.y, w0.z, w0.w, w1.x, w1.y, w1.z, w1.w};
            float xv[8] = {x0.x, x0.y, x0.z, x0.w, x1.x, x1.y, x1.z, x1.w};
            #pragma unroll
            for (int i = 0; i < 8; ++i)
                #pragma unroll
                for (int j = 0; j < 8; ++j)
                    acc[i][j] += wv[i] * xv[j];
        }
        __syncthreads();
    }
    float* Cb = g_C + (size_t)b * Mrows * M3;
    #pragma unroll
    for (int i = 0; i < 8; ++i) {
        int row = m0 + ty * 8 + i;
        if (row < Mrows) {
            float* rowp = &Cb[(size_t)row * M3 + n0 + tx * 8];
            *reinterpret_cast<float4*>(rowp)     = make_float4(acc[i][0], acc[i][1], acc[i][2], acc[i][3]);
            *reinterpret_cast<float4*>(rowp + 4) = make_float4(acc[i][4], acc[i][5], acc[i][6], acc[i][7]);
        }
    }
}

// ---------------- leaky VN nonlinearity + mean over k neighbors ----------------
template <int CCV>
__global__ void leakymean_kernel(int Co, int outOff, int nch) {
    int t = blockIdx.x * blockDim.x + threadIdx.x;
    if (t >= NB * NP * nch) return;
    int n   = t % NP;
    int tmp = t / NP;
    int ch  = tmp % nch;
    int b   = tmp / nch;

    const int4* ib4 = reinterpret_cast<const int4*>(g_idx + ((size_t)b * NP + n) * KNN);
    int idx[KNN];
    #pragma unroll
    for (int q = 0; q < 5; ++q) {
        int4 w = ib4[q];
        idx[4 * q + 0] = w.x; idx[4 * q + 1] = w.y; idx[4 * q + 2] = w.z; idx[4 * q + 3] = w.w;
    }

    const float* Cb = g_C + (size_t)b * 4 * Co * M3;
    const float inv = 1.f / (float)KNN;

    #pragma unroll
    for (int cc = 0; cc < CCV; ++cc) {
        int co = ch * CCV + cc;
        if (co >= Co) break;
        const float* Af = Cb + (size_t)co * M3;
        const float* Bf = Cb + (size_t)(Co + co) * M3;
        const float* Ad = Cb + (size_t)(2 * Co + co) * M3;
        const float* Bd = Cb + (size_t)(3 * Co + co) * M3;
        float bf0 = Bf[n], bf1 = Bf[NP + n], bf2 = Bf[2 * NP + n];
        float bd0 = Bd[n], bd1 = Bd[NP + n], bd2 = Bd[2 * NP + n];
        float a0 = 0.f, a1 = 0.f, a2 = 0.f;
        #pragma unroll
        for (int j = 0; j < KNN; ++j) {
            int m = idx[j];
            float p0 = Af[m] + bf0, p1 = Af[NP + m] + bf1, p2 = Af[2 * NP + m] + bf2;
            float d0 = Ad[m] + bd0, d1 = Ad[NP + m] + bd1, d2 = Ad[2 * NP + m] + bd2;
            float dot = p0 * d0 + p1 * d1 + p2 * d2;
            if (dot >= 0.f) {
                a0 += p0; a1 += p1; a2 += p2;
            } else {
                float dsq = d0 * d0 + d1 * d1 + d2 * d2;
                float s = 0.8f * dot / (dsq + EPSV);
                a0 += p0 - s * d0; a1 += p1 - s * d1; a2 += p2 - s * d2;
            }
        }
        float* ob = g_xcat + ((size_t)b * 169 + outOff + co) * M3 + n;
        ob[0]      = a0 * inv;
        ob[NP]     = a1 * inv;
        ob[2 * NP] = a2 * inv;
    }
}

// ---------------- final: layer4 nonlinearity + mean over N -> out (B,341,3) -----
__global__ void final_kernel(float* __restrict__ out) {
    int co = blockIdx.x;   // 0..340
    int b  = blockIdx.y;
    const float* Cb = g_C + (size_t)b * 342 * M3;
    const float* P  = Cb + (size_t)co * M3;
    const float* Dv = Cb + (size_t)341 * M3;
    float a0 = 0.f, a1 = 0.f, a2 = 0.f;
    for (int n = threadIdx.x; n < NP; n += 128) {
        float p0 = P[n], p1 = P[NP + n], p2 = P[2 * NP + n];
        float d0 = Dv[n], d1 = Dv[NP + n], d2 = Dv[2 * NP + n];
        float dot = p0 * d0 + p1 * d1 + p2 * d2;
        if (dot >= 0.f) {
            a0 += p0; a1 += p1; a2 += p2;
        } else {
            float dsq = d0 * d0 + d1 * d1 + d2 * d2;
            float s = 0.8f * dot / (dsq + EPSV);
            a0 += p0 - s * d0; a1 += p1 - s * d1; a2 += p2 - s * d2;
        }
    }
    __shared__ float s0[128], s1[128], s2[128];
    int t = threadIdx.x;
    s0[t] = a0; s1[t] = a1; s2[t] = a2;
    __syncthreads();
    for (int s = 64; s > 0; s >>= 1) {
        if (t < s) { s0[t] += s0[t + s]; s1[t] += s1[t + s]; s2[t] += s2[t + s]; }
        __syncthreads();
    }
    if (t == 0) {
        const float inv = 1.f / (float)NP;
        float* o = out + ((size_t)b * 341 + co) * 3;
        o[0] = s0[0] * inv;
        o[1] = s1[0] * inv;
        o[2] = s2[0] * inv;
    }
}

// ---------------- host orchestration (single stream, linear) ----------------
extern "C" void kernel_launch(void* const* d_in, const int* in_sizes, int n_in,
                              void* d_out, int out_size) {
    (void)in_sizes; (void)n_in; (void)out_size;
    const float* x   = (const float*)d_in[0];
    const float* Wf[5] = {(const float*)d_in[1], (const float*)d_in[3], (const float*)d_in[5],
                          (const float*)d_in[7], (const float*)d_in[9]};
    const float* Wd[5] = {(const float*)d_in[2], (const float*)d_in[4], (const float*)d_in[6],
                          (const float*)d_in[8], (const float*)d_in[10]};
    float* out = (float*)d_out;

    void* p_xcat_v = nullptr;
    cudaGetSymbolAddress(&p_xcat_v, g_xcat);
    const float* xcat = (const float*)p_xcat_v;

    const int   Ds[4]     = {1, 21, 21, 42};
    const int   Cos[4]    = {21, 21, 42, 85};
    const int   offIn[4]  = {0, 0, 21, 42};
    const int   offOut[4] = {0, 21, 42, 84};

    for (int L = 0; L < 4; ++L) {
        int D = Ds[L], Co = Cos[L];
        const float* Xin = (L == 0) ? x : xcat;
        int Ctot = (L == 0) ? 1 : 169;
        int F = 3 * D;
        int Mrows = 4 * Co;

        {   // weight prep
            int tot = 4 * Co * D;
            prepw_kernel<<<(tot + 255) / 256, 256>>>(Wf[L], Wd[L], Co, D);
        }
        negdist_kernel<<<dim3(36, 1, NB), 256>>>(Xin, Ctot, offIn[L], F);
        topk_kernel<<<NB * NP / 2, 256>>>();
        gemm_wx<<<dim3(M3 / 128, (Mrows + 127) / 128, NB), 256>>>(Xin, Ctot, offIn[L], Mrows, D);
        if (Co <= 21) {
            int nch = Co;                       // CCV = 1
            int tot = NB * NP * nch;
            leakymean_kernel<1><<<(tot + 255) / 256, 256>>>(Co, offOut[L], nch);
        } else {
            int nch = (Co + 3) / 4;             // CCV = 4
            int tot = NB * NP * nch;
            leakymean_kernel<4><<<(tot + 255) / 256, 256>>>(Co, offOut[L], nch);
        }
    }

    prepw4_kernel<<<(342 * 169 + 255) / 256, 256>>>(Wf[4], Wd[4]);
    gemm_wx<<<dim3(M3 / 128, (342 + 127) / 128, NB), 256>>>(xcat, 169, 0, 342, 169);
    final_kernel<<<dim3(341, NB), 128>>>(out);
}

// round 15
// speedup vs baseline: 1.0906x; 1.0906x over previous
#include <cuda_runtime.h>
#include <cstdint>

#define NB 8
#define NP 1024
#define KNN 20
#define M3 (3*NP)
#define EPSV 1e-6f

// ---------------- scratch (device globals; no allocations allowed) ----------------
__device__ float g_nd[(size_t)NB*NP*NP];     // neg-distance matrix (B,N,N)
__device__ int   g_idx[NB*NP*KNN];           // knn indices
__device__ float g_Ws[342*169];              // stacked/transformed weights (max 342x169)
__device__ float g_C[(size_t)NB*342*M3];     // gemm output (Af/Bf/Ad/Bd stacked, or p/d for layer4)
__device__ float g_xcat[(size_t)NB*169*M3];  // concat feature buffer (B,169,3,N)

// ---------------- weight prep: stack [WfA; WfB-WfA; WdA; WdB-WdA] -> (4Co x D) ----
__global__ void prepw_kernel(const float* __restrict__ Wf, const float* __restrict__ Wd,
                             int Co, int D) {
    int t = blockIdx.x * blockDim.x + threadIdx.x;
    int total = 4 * Co * D;
    if (t >= total) return;
    int ci = t % D;
    int r  = t / D;
    float v;
    if (r < Co) {
        v = Wf[r * 2 * D + ci];
    } else if (r < 2 * Co) {
        int co = r - Co;
        v = Wf[co * 2 * D + D + ci] - Wf[co * 2 * D + ci];
    } else if (r < 3 * Co) {
        int co = r - 2 * Co;
        v = Wd[co * 2 * D + ci];
    } else {
        int co = r - 3 * Co;
        v = Wd[co * 2 * D + D + ci] - Wd[co * 2 * D + ci];
    }
    g_Ws[t] = v;
}

// layer4: stack [Wf4 (341x169); Wd4 (1x169)] -> (342x169)
__global__ void prepw4_kernel(const float* __restrict__ Wf, const float* __restrict__ Wd) {
    int t = blockIdx.x * blockDim.x + threadIdx.x;
    const int nf = 341 * 169;
    const int total = 342 * 169;
    if (t >= total) return;
    g_Ws[t] = (t < nf) ? Wf[t] : Wd[t - nf];
}

// ---------------- negdist (SYMMETRIC): nd[i][j] = 2*<xi,xj> - xx_i - xx_j --------
__global__ __launch_bounds__(256) void negdist_kernel(const float* __restrict__ X,
                                                      int Ctot, int coff, int F) {
    int b = blockIdx.z;
    int bi = 0, rem = blockIdx.x;
    while (rem >= 8 - bi) { rem -= 8 - bi; ++bi; }
    int bj = bi + rem;
    int i0 = bi * 128;
    int j0 = bj * 128;

    __shared__ float sA[8][128];
    __shared__ float sB[8][128];
    __shared__ float sT[16][132];     // transpose staging; 132-float stride = 528B = 33*16B
    const int t  = threadIdx.x;
    const int tx = t & 15, ty = t >> 4;
    const int lk = t >> 5;
    const int lc = (t & 31) * 4;
    float acc[8][8] = {};
    float xxa[8] = {}, xxb[8] = {};
    const float* Xb = X + (size_t)(b * Ctot + coff) * M3;
    const int nch = (F + 7) / 8;
    for (int c = 0; c < nch; ++c) {
        int f = c * 8 + lk;
        float4 va = make_float4(0.f, 0.f, 0.f, 0.f), vb = va;
        if (f < F) {
            va = *reinterpret_cast<const float4*>(&Xb[(size_t)f * NP + i0 + lc]);
            vb = *reinterpret_cast<const float4*>(&Xb[(size_t)f * NP + j0 + lc]);
        }
        *reinterpret_cast<float4*>(&sA[lk][lc]) = va;
        *reinterpret_cast<float4*>(&sB[lk][lc]) = vb;
        __syncthreads();
        #pragma unroll
        for (int kk = 0; kk < 8; ++kk) {
            float4 a0 = *reinterpret_cast<const float4*>(&sA[kk][ty * 8]);
            float4 a1 = *reinterpret_cast<const float4*>(&sA[kk][ty * 8 + 4]);
            float4 b0 = *reinterpret_cast<const float4*>(&sB[kk][tx * 8]);
            float4 b1 = *reinterpret_cast<const float4*>(&sB[kk][tx * 8 + 4]);
            float av[8] = {a0.x, a0.y, a0.z, a0.w, a1.x, a1.y, a1.z, a1.w};
            float bv[8] = {b0.x, b0.y, b0.z, b0.w, b1.x, b1.y, b1.z, b1.w};
            #pragma unroll
            for (int i = 0; i < 8; ++i) {
                xxa[i] += av[i] * av[i];
                xxb[i] += bv[i] * bv[i];
                #pragma unroll
                for (int j = 0; j < 8; ++j)
                    acc[i][j] += av[i] * bv[j];
            }
        }
        __syncthreads();
    }
    float* ndb = g_nd + (size_t)b * NP * NP;

    #pragma unroll
    for (int i = 0; i < 8; ++i) {
        int ii = i0 + ty * 8 + i;
        float xi = xxa[i];
        float4 v0, v1;
        v0.x = 2.f * acc[i][0] - xi - xxb[0];
        v0.y = 2.f * acc[i][1] - xi - xxb[1];
        v0.z = 2.f * acc[i][2] - xi - xxb[2];
        v0.w = 2.f * acc[i][3] - xi - xxb[3];
        v1.x = 2.f * acc[i][4] - xi - xxb[4];
        v1.y = 2.f * acc[i][5] - xi - xxb[5];
        v1.z = 2.f * acc[i][6] - xi - xxb[6];
        v1.w = 2.f * acc[i][7] - xi - xxb[7];
        float* rowp = &ndb[(size_t)ii * NP + j0 + tx * 8];
        *reinterpret_cast<float4*>(rowp)     = v0;
        *reinterpret_cast<float4*>(rowp + 4) = v1;
    }

    if (bi != bj) {
        __syncthreads();
        #pragma unroll 1
        for (int c = 0; c < 8; ++c) {
            if ((tx >> 1) == c) {
                int colbase = (tx & 1) * 8;
                #pragma unroll
                for (int j = 0; j < 8; ++j) {
                    #pragma unroll
                    for (int i = 0; i < 8; ++i) {
                        sT[colbase + j][ty * 8 + i] = (2.f * acc[i][j] - xxb[j]) - xxa[i];
                    }
                }
            }
            __syncthreads();
            {
                int r    = t >> 4;
                int colS = (t & 15) * 8;
                float4 u0 = *reinterpret_cast<const float4*>(&sT[r][colS]);
                float4 u1 = *reinterpret_cast<const float4*>(&sT[r][colS + 4]);
                float* orow = &ndb[(size_t)(j0 + c * 16 + r) * NP + i0 + colS];
                *reinterpret_cast<float4*>(orow)     = u0;
                *reinterpret_cast<float4*>(orow + 4) = u1;
            }
            __syncthreads();
        }
    }
}

// ---------------- topk: two-level radix select (order-free set; exact tie-break) --
// Level 1: top-10-bit bins isolate the boundary bin. Level 2: because nd values
// cluster in few exponents, the boundary bin is large; refine by key bits [12:22)
// (all candidates share the top 10 bits, so this ordering is exact on the 22-bit
// prefix). Sub-bin winners are bulk-scattered; only the tiny sub-boundary bin goes
// through the exact (value desc, index asc) full-key loop.
__device__ __forceinline__ unsigned int f2key(float v) {
    unsigned int u = __float_as_uint(v);
    return (u & 0x80000000u) ? ~u : (u | 0x80000000u);   // monotonic: bigger float -> bigger key
}

__global__ __launch_bounds__(256) void topk_kernel() {
    const int row = blockIdx.x;            // b*NP + n
    __shared__ int hist[1024];             // bin histogram (reused for both levels)
    __shared__ int cand_key_i[NP];         // boundary-bin candidates (keys, 0 = removed)
    __shared__ int cand_idx[NP];
    __shared__ int sP[256];                // group partials (4 bins per group)
    __shared__ int sG[256];                // suffix sums per group
    __shared__ int wsum[8];
    __shared__ int sh_B, sh_c, sh_ncand, sh_nout, sh_ncand2;

    const int t   = threadIdx.x;
    const int wid = t >> 5, lid = t & 31;

    // issue global load early (contiguous float4 per thread), then zero hist
    const float4 v = reinterpret_cast<const float4*>(g_nd + (size_t)row * NP)[t];
    reinterpret_cast<int4*>(hist)[t] = make_int4(0, 0, 0, 0);
    if (t == 0) { sh_ncand = 0; sh_nout = 0; sh_ncand2 = 0; }
    __syncthreads();

    unsigned int keys[4];
    keys[0] = f2key(v.x); keys[1] = f2key(v.y); keys[2] = f2key(v.z); keys[3] = f2key(v.w);
    #pragma unroll
    for (int i = 0; i < 4; ++i) atomicAdd(&hist[keys[i] >> 22], 1);
    __syncthreads();

    {
        int4 h4 = reinterpret_cast<const int4*>(hist)[t];
        sP[t] = h4.x + h4.y + h4.z + h4.w;
    }
    __syncthreads();

    {   // suffix sum over 256 groups via reversed inclusive shuffle-scan
        int s = sP[255 - t];
        #pragma unroll
        for (int off = 1; off < 32; off <<= 1) {
            int n = __shfl_up_sync(0xffffffffu, s, off);
            if (lid >= off) s += n;
        }
        if (lid == 31) wsum[wid] = s;
        __syncthreads();
        int add = 0;
        #pragma unroll
        for (int w = 0; w < 8; ++w) if (w < wid) add += wsum[w];
        sG[255 - t] = s + add;
    }
    __syncthreads();

    {   // locate level-1 boundary bin
        int Gt    = sG[t];
        int Gnext = (t < 255) ? sG[t + 1] : 0;
        if (Gt >= KNN && Gnext < KNN) {
            int cum = Gnext;
            int B = 4 * t;
            #pragma unroll
            for (int b = 4 * t + 3; b >= 4 * t; --b) {
                int h = hist[b];
                if (cum + h >= KNN) { B = b; break; }
                cum += h;
            }
            sh_B = B; sh_c = cum;
        }
    }
    __syncthreads();
    const int B = sh_B;
    int* outp = g_idx + (size_t)row * KNN;

    // scatter definite winners (bins > B), collect boundary-bin candidates
    #pragma unroll
    for (int i = 0; i < 4; ++i) {
        int j = 4 * t + i;
        int bin = keys[i] >> 22;
        if (bin > B) {
            int pos = atomicAdd(&sh_nout, 1);
            outp[pos] = j;
        } else if (bin == B) {
            int pos = atomicAdd(&sh_ncand, 1);
            cand_key_i[pos] = (int)keys[i];   // sentinel 0 only matches a NaN pattern
            cand_idx[pos] = j;
        }
    }
    __syncthreads();

    // ---------- level 2: refine boundary bin by key bits [12:22) ----------
    const int m = sh_ncand;
    const int rneed = KNN - sh_c;           // 0 < rneed <= m

    // cache my candidates into registers (<=4), zero hist for level-2
    int myk[4], myi[4];
    int myn = 0;
    for (int j = t; j < m; j += 256) {
        myk[myn] = cand_key_i[j];
        myi[myn] = cand_idx[j];
        ++myn;
    }
    reinterpret_cast<int4*>(hist)[t] = make_int4(0, 0, 0, 0);
    __syncthreads();

    for (int q = 0; q < myn; ++q)
        atomicAdd(&hist[((unsigned int)myk[q] >> 12) & 1023], 1);
    __syncthreads();

    {
        int4 h4 = reinterpret_cast<const int4*>(hist)[t];
        sP[t] = h4.x + h4.y + h4.z + h4.w;
    }
    __syncthreads();
    {
        int s = sP[255 - t];
        #pragma unroll
        for (int off = 1; off < 32; off <<= 1) {
            int n = __shfl_up_sync(0xffffffffu, s, off);
            if (lid >= off) s += n;
        }
        if (lid == 31) wsum[wid] = s;
        __syncthreads();
        int add = 0;
        #pragma unroll
        for (int w = 0; w < 8; ++w) if (w < wid) add += wsum[w];
        sG[255 - t] = s + add;
    }
    __syncthreads();
    {   // locate level-2 boundary bin (threshold = rneed)
        int Gt    = sG[t];
        int Gnext = (t < 255) ? sG[t + 1] : 0;
        if (Gt >= rneed && Gnext < rneed) {
            int cum = Gnext;
            int B2 = 4 * t;
            #pragma unroll
            for (int b = 4 * t + 3; b >= 4 * t; --b) {
                int h = hist[b];
                if (cum + h >= rneed) { B2 = b; break; }
                cum += h;
            }
            sh_B = B2;
        }
    }
    __syncthreads();
    const int B2 = sh_B;

    // rescatter: sub-bin winners straight to output; sub-boundary bin -> new cand list
    for (int q = 0; q < myn; ++q) {
        int bin2 = ((unsigned int)myk[q] >> 12) & 1023;
        if (bin2 > B2) {
            int pos = atomicAdd(&sh_nout, 1);
            outp[pos] = myi[q];
        } else if (bin2 == B2) {
            int pos = atomicAdd(&sh_ncand2, 1);
            cand_key_i[pos] = myk[q];
            cand_idx[pos] = myi[q];
        }
    }
    __syncthreads();

    // exact selection over the (tiny) residual set: warp 0 only
    if (wid == 0) {
        const int m2 = sh_ncand2;
        const int placed = sh_nout;
        const int rneed2 = KNN - placed;     // 0 < rneed2 <= m2
        for (int sel = 0; sel < rneed2; ++sel) {
            unsigned long long best = 0ull;
            for (int j = lid; j < m2; j += 32) {
                unsigned int key = (unsigned int)cand_key_i[j];
                if (key != 0u) {
                    unsigned long long p = ((unsigned long long)key << 32)
                                         | ((unsigned long long)(1023 - cand_idx[j]) << 10)
                                         | (unsigned int)j;
                    if (p > best) best = p;
                }
            }
            #pragma unroll
            for (int off = 16; off > 0; off >>= 1) {
                unsigned long long o = __shfl_xor_sync(0xffffffffu, best, off);
                if (o > best) best = o;
            }
            int candpos = (int)(best & 1023ull);
            if (lid == 0) {
                outp[placed + sel] = cand_idx[candpos];
                cand_key_i[candpos] = 0;
            }
            __syncwarp();
        }
    }
}

// ---------------- gemm: C[b, row, m] = sum_ci Ws[row, ci] * X[b, ci, m] ----------
// 128x128 tile, 8x8 register microtile, BK=8.
__global__ __launch_bounds__(256) void gemm_wx(const float* __restrict__ X, int Ctot, int xOff,
                                               int Mrows, int K) {
    int b  = blockIdx.z;
    int m0 = blockIdx.y * 128;
    int n0 = blockIdx.x * 128;
    __shared__ float sW[8][128];
    __shared__ float sX[8][128];
    const int t  = threadIdx.x;
    const int tx = t & 15, ty = t >> 4;
    const int lk = t >> 5;
    const int lc = (t & 31) * 4;
    float acc[8][8] = {};
    const float* Xb = X + (size_t)(b * Ctot + xOff) * M3;
    const int nch = (K + 7) / 8;
    for (int c = 0; c < nch; ++c) {
        #pragma unroll
        for (int i = t; i < 1024; i += 256) {
            int kk = i & 7, mo = i >> 3;
            int row = m0 + mo, col = c * 8 + kk;
            sW[kk][mo] = (row < Mrows && col < K) ? g_Ws[row * K + col] : 0.f;
        }
        int f = c * 8 + lk;
        float4 vx = make_float4(0.f, 0.f, 0.f, 0.f);
        if (f < K) vx = *reinterpret_cast<const float4*>(&Xb[(size_t)f * M3 + n0 + lc]);
        *reinterpret_cast<float4*>(&sX[lk][lc]) = vx;
        __syncthreads();
        #pragma unroll
        for (int kk = 0; kk < 8; ++kk) {
            float4 w0 = *reinterpret_cast<const float4*>(&sW[kk][ty * 8]);
            float4 w1 = *reinterpret_cast<const float4*>(&sW[kk][ty * 8 + 4]);
            float4 x0 = *reinterpret_cast<const float4*>(&sX[kk][tx * 8]);
            float4 x1 = *reinterpret_cast<const float4*>(&sX[kk][tx * 8 + 4]);
            float wv[8] = {w0.x, w0.y, w0.z, w0.w, w1.x, w1.y, w1.z, w1.w};
            float xv[8] = {x0.x, x0.y, x0.z, x0.w, x1.x, x1.y, x1.z, x1.w};
            #pragma unroll
            for (int i = 0; i < 8; ++i)
                #pragma unroll
                for (int j = 0; j < 8; ++j)
                    acc[i][j] += wv[i] * xv[j];
        }
        __syncthreads();
    }
    float* Cb = g_C + (size_t)b * Mrows * M3;
    #pragma unroll
    for (int i = 0; i < 8; ++i) {
        int row = m0 + ty * 8 + i;
        if (row < Mrows) {
            float* rowp = &Cb[(size_t)row * M3 + n0 + tx * 8];
            *reinterpret_cast<float4*>(rowp)     = make_float4(acc[i][0], acc[i][1], acc[i][2], acc[i][3]);
            *reinterpret_cast<float4*>(rowp + 4) = make_float4(acc[i][4], acc[i][5], acc[i][6], acc[i][7]);
        }
    }
}

// ---------------- leaky VN nonlinearity + mean over k neighbors ----------------
template <int CCV>
__global__ void leakymean_kernel(int Co, int outOff, int nch) {
    int t = blockIdx.x * blockDim.x + threadIdx.x;
    if (t >= NB * NP * nch) return;
    int n   = t % NP;
    int tmp = t / NP;
    int ch  = tmp % nch;
    int b   = tmp / nch;

    const int4* ib4 = reinterpret_cast<const int4*>(g_idx + ((size_t)b * NP + n) * KNN);
    int idx[KNN];
    #pragma unroll
    for (int q = 0; q < 5; ++q) {
        int4 w = ib4[q];
        idx[4 * q + 0] = w.x; idx[4 * q + 1] = w.y; idx[4 * q + 2] = w.z; idx[4 * q + 3] = w.w;
    }

    const float* Cb = g_C + (size_t)b * 4 * Co * M3;
    const float inv = 1.f / (float)KNN;

    #pragma unroll
    for (int cc = 0; cc < CCV; ++cc) {
        int co = ch * CCV + cc;
        if (co >= Co) break;
        const float* Af = Cb + (size_t)co * M3;
        const float* Bf = Cb + (size_t)(Co + co) * M3;
        const float* Ad = Cb + (size_t)(2 * Co + co) * M3;
        const float* Bd = Cb + (size_t)(3 * Co + co) * M3;
        float bf0 = Bf[n], bf1 = Bf[NP + n], bf2 = Bf[2 * NP + n];
        float bd0 = Bd[n], bd1 = Bd[NP + n], bd2 = Bd[2 * NP + n];
        float a0 = 0.f, a1 = 0.f, a2 = 0.f;
        #pragma unroll
        for (int j = 0; j < KNN; ++j) {
            int m = idx[j];
            float p0 = Af[m] + bf0, p1 = Af[NP + m] + bf1, p2 = Af[2 * NP + m] + bf2;
            float d0 = Ad[m] + bd0, d1 = Ad[NP + m] + bd1, d2 = Ad[2 * NP + m] + bd2;
            float dot = p0 * d0 + p1 * d1 + p2 * d2;
            if (dot >= 0.f) {
                a0 += p0; a1 += p1; a2 += p2;
            } else {
                float dsq = d0 * d0 + d1 * d1 + d2 * d2;
                float s = 0.8f * dot / (dsq + EPSV);
                a0 += p0 - s * d0; a1 += p1 - s * d1; a2 += p2 - s * d2;
            }
        }
        float* ob = g_xcat + ((size_t)b * 169 + outOff + co) * M3 + n;
        ob[0]      = a0 * inv;
        ob[NP]     = a1 * inv;
        ob[2 * NP] = a2 * inv;
    }
}

// ---------------- final: layer4 nonlinearity + mean over N -> out (B,341,3) -----
__global__ void final_kernel(float* __restrict__ out) {
    int co = blockIdx.x;   // 0..340
    int b  = blockIdx.y;
    const float* Cb = g_C + (size_t)b * 342 * M3;
    const float* P  = Cb + (size_t)co * M3;
    const float* Dv = Cb + (size_t)341 * M3;
    float a0 = 0.f, a1 = 0.f, a2 = 0.f;
    for (int n = threadIdx.x; n < NP; n += 128) {
        float p0 = P[n], p1 = P[NP + n], p2 = P[2 * NP + n];
        float d0 = Dv[n], d1 = Dv[NP + n], d2 = Dv[2 * NP + n];
        float dot = p0 * d0 + p1 * d1 + p2 * d2;
        if (dot >= 0.f) {
            a0 += p0; a1 += p1; a2 += p2;
        } else {
            float dsq = d0 * d0 + d1 * d1 + d2 * d2;
            float s = 0.8f * dot / (dsq + EPSV);
            a0 += p0 - s * d0; a1 += p1 - s * d1; a2 += p2 - s * d2;
        }
    }
    __shared__ float s0[128], s1[128], s2[128];
    int t = threadIdx.x;
    s0[t] = a0; s1[t] = a1; s2[t] = a2;
    __syncthreads();
    for (int s = 64; s > 0; s >>= 1) {
        if (t < s) { s0[t] += s0[t + s]; s1[t] += s1[t + s]; s2[t] += s2[t + s]; }
        __syncthreads();
    }
    if (t == 0) {
        const float inv = 1.f / (float)NP;
        float* o = out + ((size_t)b * 341 + co) * 3;
        o[0] = s0[0] * inv;
        o[1] = s1[0] * inv;
        o[2] = s2[0] * inv;
    }
}

// ---------------- host orchestration (single stream, linear) ----------------
extern "C" void kernel_launch(void* const* d_in, const int* in_sizes, int n_in,
                              void* d_out, int out_size) {
    (void)in_sizes; (void)n_in; (void)out_size;
    const float* x   = (const float*)d_in[0];
    const float* Wf[5] = {(const float*)d_in[1], (const float*)d_in[3], (const float*)d_in[5],
                          (const float*)d_in[7], (const float*)d_in[9]};
    const float* Wd[5] = {(const float*)d_in[2], (const float*)d_in[4], (const float*)d_in[6],
                          (const float*)d_in[8], (const float*)d_in[10]};
    float* out = (float*)d_out;

    void* p_xcat_v = nullptr;
    cudaGetSymbolAddress(&p_xcat_v, g_xcat);
    const float* xcat = (const float*)p_xcat_v;

    const int   Ds[4]     = {1, 21, 21, 42};
    const int   Cos[4]    = {21, 21, 42, 85};
    const int   offIn[4]  = {0, 0, 21, 42};
    const int   offOut[4] = {0, 21, 42, 84};

    for (int L = 0; L < 4; ++L) {
        int D = Ds[L], Co = Cos[L];
        const float* Xin = (L == 0) ? x : xcat;
        int Ctot = (L == 0) ? 1 : 169;
        int F = 3 * D;
        int Mrows = 4 * Co;

        {   // weight prep
            int tot = 4 * Co * D;
            prepw_kernel<<<(tot + 255) / 256, 256>>>(Wf[L], Wd[L], Co, D);
        }
        negdist_kernel<<<dim3(36, 1, NB), 256>>>(Xin, Ctot, offIn[L], F);
        topk_kernel<<<NB * NP, 256>>>();
        gemm_wx<<<dim3(M3 / 128, (Mrows + 127) / 128, NB), 256>>>(Xin, Ctot, offIn[L], Mrows, D);
        if (Co <= 21) {
            int nch = Co;                       // CCV = 1
            int tot = NB * NP * nch;
            leakymean_kernel<1><<<(tot + 255) / 256, 256>>>(Co, offOut[L], nch);
        } else {
            int nch = (Co + 3) / 4;             // CCV = 4
            int tot = NB * NP * nch;
            leakymean_kernel<4><<<(tot + 255) / 256, 256>>>(Co, offOut[L], nch);
        }
    }

    prepw4_kernel<<<(342 * 169 + 255) / 256, 256>>>(Wf[4], Wd[4]);
    gemm_wx<<<dim3(M3 / 128, (342 + 127) / 128, NB), 256>>>(xcat, 169, 0, 342, 169);
    final_kernel<<<dim3(341, NB), 128>>>(out);
}